// round 1
// baseline (speedup 1.0000x reference)
#include <cuda_runtime.h>
#include <cuda_bf16.h>
#include <cstdint>

// Problem geometry (from reference):
//   x: (8, 506, 506, 32) f32, mask: (8, 506, 506, 1) f32,
//   kernel: (3,3,32,32) f32 [ky][kx][ci][co], bias: (32,) f32
//   out: (8, 504, 504, 32) f32
// out[n,R,C,co] = active[n,R/14,C/14] * (bias[co] + sum_{dy,dx,ci} x[n,R+dy,C+dx,ci]*k[dy,dx,ci,co])
// active[n,bi,bj] = max over mask[n, bi*14 .. bi*14+15, bj*14 .. bj*14+15] > 0.5

#define N_IMG   8
#define H_IN    506
#define W_IN    506
#define CIN     32
#define COUT    32
#define H_OUT   504
#define W_OUT   504
#define NBH     36
#define NBW     36
#define TILE    16

// scratch: per-block active flags as float 0/1  (no cudaMalloc allowed)
__device__ float g_active[N_IMG * NBH * NBW];

// ---------------------------------------------------------------------------
// packed f32x2 helpers (sm_103a FFMA2 — only reachable via PTX)
// ---------------------------------------------------------------------------
__device__ __forceinline__ void ffma2(uint64_t& acc, uint64_t a, uint64_t b) {
    asm("fma.rn.f32x2 %0, %1, %2, %0;" : "+l"(acc) : "l"(a), "l"(b));
}
__device__ __forceinline__ uint64_t pack2(float v) {
    uint64_t r;
    asm("mov.b64 %0, {%1, %1};" : "=l"(r) : "f"(v));
    return r;
}
__device__ __forceinline__ void unpack2(uint64_t v, float& lo, float& hi) {
    asm("mov.b64 {%0, %1}, %2;" : "=f"(lo), "=f"(hi) : "l"(v));
}

// ---------------------------------------------------------------------------
// Kernel 1: per 16x16 mask block max -> active flag (float 0/1)
// ---------------------------------------------------------------------------
__global__ void __launch_bounds__(256) mask_kernel(const float* __restrict__ mask) {
    __shared__ float red[256];
    int b = blockIdx.x;                 // 0 .. N*NBH*NBW-1
    int n  = b / (NBH * NBW);
    int rem = b % (NBH * NBW);
    int bi = rem / NBW;
    int bj = rem % NBW;
    int tid = threadIdx.x;
    int rr = tid >> 4, cc = tid & 15;
    int R = bi * 14 + rr;
    int C = bj * 14 + cc;
    float v = mask[(n * H_IN + R) * W_IN + C];
    red[tid] = v;
    __syncthreads();
    #pragma unroll
    for (int s = 128; s > 0; s >>= 1) {
        if (tid < s) red[tid] = fmaxf(red[tid], red[tid + s]);
        __syncthreads();
    }
    if (tid == 0) g_active[b] = (red[0] > 0.5f) ? 1.0f : 0.0f;
}

// ---------------------------------------------------------------------------
// Kernel 2: valid 3x3 conv, 16x16 output tile per CTA, 256 threads.
// Thread = one output pixel, all 32 couts as 16 packed f32x2 accumulators.
// smem: weights [9][32][32] (36864B, verbatim copy) + x tile [32][18][19]
// (channel-major, padded col stride 19 for conflict-free LDS).
// ---------------------------------------------------------------------------
#define W_SMEM_FLOATS  (9 * 32 * 32)          // 9216
#define X_ROWP         19
#define X_CI_STRIDE    (18 * X_ROWP)          // 342
#define X_SMEM_FLOATS  (32 * X_CI_STRIDE)     // 10944
#define SMEM_BYTES     ((W_SMEM_FLOATS + X_SMEM_FLOATS) * 4)   // 80640

__global__ void __launch_bounds__(256, 2) conv_kernel(
    const float* __restrict__ x,
    const float* __restrict__ kern,
    const float* __restrict__ bias,
    float* __restrict__ out)
{
    extern __shared__ float smem[];
    float* w_s = smem;                      // [tap][ci][cout]
    float* x_s = smem + W_SMEM_FLOATS;      // [ci][18][19]

    const int n  = blockIdx.z;
    const int R0 = blockIdx.y * TILE;
    const int C0 = blockIdx.x * TILE;
    const int tid = threadIdx.x;

    // --- load weights (contiguous 9216 floats) ---
    {
        const float4* kg = (const float4*)kern;
        float4* wg = (float4*)w_s;
        #pragma unroll
        for (int i = 0; i < 9; i++)
            wg[tid + 256 * i] = kg[tid + 256 * i];
    }

    // --- load x tile: 18x18 pixels x 32 ch, transpose NHWC -> [ci][r][c] ---
    for (int idx = tid; idx < 18 * 18 * 8; idx += 256) {
        int p = idx >> 3;          // pixel 0..323
        int q = idx & 7;           // float4 group over ci
        int pr = p / 18, pc = p % 18;
        int gr = R0 + pr, gc = C0 + pc;
        if (gr < H_IN && gc < W_IN) {
            float4 v = *(const float4*)&x[((n * H_IN + gr) * W_IN + gc) * CIN + q * 4];
            int base = pr * X_ROWP + pc;
            x_s[(q * 4 + 0) * X_CI_STRIDE + base] = v.x;
            x_s[(q * 4 + 1) * X_CI_STRIDE + base] = v.y;
            x_s[(q * 4 + 2) * X_CI_STRIDE + base] = v.z;
            x_s[(q * 4 + 3) * X_CI_STRIDE + base] = v.w;
        }
    }
    __syncthreads();

    const int py = tid >> 4, px = tid & 15;

    uint64_t acc[16];
    #pragma unroll
    for (int k = 0; k < 16; k++) acc[k] = 0ull;   // (0.f, 0.f)

    const float* xb = x_s + py * X_ROWP + px;

    #pragma unroll
    for (int tap = 0; tap < 9; tap++) {
        const int dy = tap / 3, dx = tap % 3;
        const float* xt = xb + dy * X_ROWP + dx;
        const ulonglong2* wt = (const ulonglong2*)(w_s + tap * (32 * 32));
        #pragma unroll 2
        for (int ci = 0; ci < 32; ci++) {
            uint64_t xx = pack2(xt[ci * X_CI_STRIDE]);
            const ulonglong2* wr = wt + ci * 8;     // 32 floats = 8 x ulonglong2
            #pragma unroll
            for (int j = 0; j < 8; j++) {
                ulonglong2 w2 = wr[j];
                ffma2(acc[2 * j    ], xx, w2.x);    // couts 4j, 4j+1
                ffma2(acc[2 * j + 1], xx, w2.y);    // couts 4j+2, 4j+3
            }
        }
    }

    const int R = R0 + py, C = C0 + px;
    if (R < H_OUT && C < W_OUT) {
        float f = g_active[(n * NBH + R / 14) * NBW + C / 14];
        float* op = out + ((n * H_OUT + R) * W_OUT + C) * COUT;
        #pragma unroll
        for (int k = 0; k < 16; k++) {
            float lo, hi;
            unpack2(acc[k], lo, hi);
            float2 v;
            v.x = (lo + bias[2 * k    ]) * f;
            v.y = (hi + bias[2 * k + 1]) * f;
            ((float2*)op)[k] = v;
        }
    }
}

// ---------------------------------------------------------------------------
extern "C" void kernel_launch(void* const* d_in, const int* in_sizes, int n_in,
                              void* d_out, int out_size)
{
    const float* x    = (const float*)d_in[0];
    const float* mask = (const float*)d_in[1];
    const float* kern = (const float*)d_in[2];
    const float* bias = (const float*)d_in[3];
    float* out = (float*)d_out;

    (void)in_sizes; (void)n_in; (void)out_size;

    cudaFuncSetAttribute(conv_kernel,
                         cudaFuncAttributeMaxDynamicSharedMemorySize, SMEM_BYTES);

    mask_kernel<<<N_IMG * NBH * NBW, 256>>>(mask);

    dim3 grid((W_OUT + TILE - 1) / TILE, (H_OUT + TILE - 1) / TILE, N_IMG);
    conv_kernel<<<grid, 256, SMEM_BYTES>>>(x, kern, bias, out);
}

// round 2
// speedup vs baseline: 1.8885x; 1.8885x over previous
#include <cuda_runtime.h>
#include <cuda_bf16.h>
#include <cstdint>

// out[n,R,C,co] = active[n,R/14,C/14] * (bias[co] + sum_{dy,dx,ci} x[n,R+dy,C+dx,ci]*k[dy,dx,ci,co])
// (valid 3x3 conv of 506x506 -> 504x504, gated per 14x14 tile by mask-block max > 0.5)

#define N_IMG   8
#define H_IN    506
#define W_IN    506
#define CIN     32
#define COUT    32
#define H_OUT   504
#define W_OUT   504
#define NBH     36
#define NBW     36

// conv tiling: CTA = 16 rows x 32 cols of output; thread = 8 cols x 8 couts
#define TR      16
#define TC      32
#define CHUNK   16                    // ci staged per phase
#define XPITCH  36                    // floats per smem row (144B, conflict-free shift)
#define XCS     (18 * XPITCH)         // 648 floats per ci plane
#define XS_FLOATS (CHUNK * XCS)       // 10368
#define WS_FLOATS (9 * 32 * 32)       // 9216
#define SMEM_BYTES ((XS_FLOATS + WS_FLOATS) * 4)   // 78336

__device__ float g_active[N_IMG * NBH * NBW];

// ---------------- packed f32x2 helpers (sm_103a FFMA2, PTX-only) -------------
__device__ __forceinline__ void ffma2(uint64_t& acc, uint64_t a, uint64_t b) {
    asm("fma.rn.f32x2 %0, %1, %2, %0;" : "+l"(acc) : "l"(a), "l"(b));
}
__device__ __forceinline__ uint64_t pack2(float v) {
    uint64_t r;
    asm("mov.b64 %0, {%1, %1};" : "=l"(r) : "f"(v));
    return r;
}
__device__ __forceinline__ void unpack2(uint64_t v, float& lo, float& hi) {
    asm("mov.b64 {%0, %1}, %2;" : "=f"(lo), "=f"(hi) : "l"(v));
}

// ---------------- kernel 1: mask block max -> active flag -------------------
__global__ void __launch_bounds__(256) mask_kernel(const float* __restrict__ mask) {
    __shared__ float red[256];
    int b = blockIdx.x;
    int n   = b / (NBH * NBW);
    int rem = b % (NBH * NBW);
    int bi = rem / NBW, bj = rem % NBW;
    int tid = threadIdx.x;
    int rr = tid >> 4, cc = tid & 15;
    float v = mask[(n * H_IN + bi * 14 + rr) * W_IN + bj * 14 + cc];
    red[tid] = v;
    __syncthreads();
    #pragma unroll
    for (int s = 128; s > 0; s >>= 1) {
        if (tid < s) red[tid] = fmaxf(red[tid], red[tid + s]);
        __syncthreads();
    }
    if (tid == 0) g_active[b] = (red[0] > 0.5f) ? 1.0f : 0.0f;
}

// ---------------- kernel 2: conv, register-tiled 8px x 8co ------------------
__global__ void __launch_bounds__(256, 2) conv_kernel(
    const float* __restrict__ x,
    const float* __restrict__ kern,
    const float* __restrict__ bias,
    float* __restrict__ out)
{
    extern __shared__ float smem[];
    float* w_s = smem;                   // [tap][ci][co]  (verbatim HWIO)
    float* x_s = smem + WS_FLOATS;       // [ci(chunk)][18][XPITCH]

    const int n  = blockIdx.z;
    const int R0 = blockIdx.y * TR;
    const int C0 = blockIdx.x * TC;
    const int tid = threadIdx.x;

    const int cg   = tid >> 6;           // cout group 0..3 (couts cg*8..cg*8+7)
    const int g    = tid & 63;
    const int row  = g >> 2;             // 0..15
    const int c0   = (g & 3) * 8;        // 0,8,16,24

    // load weights once (9216 floats contiguous)
    {
        const float4* kg = (const float4*)kern;
        float4* wg = (float4*)w_s;
        #pragma unroll
        for (int i = 0; i < 9; i++)
            wg[tid + 256 * i] = kg[tid + 256 * i];
    }

    uint64_t acc[8][4];
    #pragma unroll
    for (int p = 0; p < 8; p++)
        #pragma unroll
        for (int j = 0; j < 4; j++) acc[p][j] = 0ull;

    #pragma unroll 1
    for (int ch = 0; ch < 2; ch++) {
        __syncthreads();
        // stage x chunk: 18 x 34 pixels, 16 ci, NHWC -> [ci][r][c]
        for (int idx = tid; idx < 18 * 34 * 4; idx += 256) {
            int p  = idx >> 2;
            int q  = idx & 3;            // float4 group within the 16-ci chunk
            int pr = p / 34, pc = p % 34;
            int gr = R0 + pr; if (gr > H_IN - 1) gr = H_IN - 1;
            int gc = C0 + pc; if (gc > W_IN - 1) gc = W_IN - 1;
            float4 v = *(const float4*)&x[((size_t)(n * H_IN + gr) * W_IN + gc) * CIN
                                          + ch * CHUNK + q * 4];
            float* d = x_s + pr * XPITCH + pc;
            d[(q * 4 + 0) * XCS] = v.x;
            d[(q * 4 + 1) * XCS] = v.y;
            d[(q * 4 + 2) * XCS] = v.z;
            d[(q * 4 + 3) * XCS] = v.w;
        }
        __syncthreads();

        #pragma unroll
        for (int dy = 0; dy < 3; dy++) {
            const float* xrow = x_s + (row + dy) * XPITCH + c0;
            #pragma unroll 2
            for (int ci = 0; ci < CHUNK; ci++) {
                const float* xp = xrow + ci * XCS;
                float4 a  = *(const float4*)xp;
                float4 b  = *(const float4*)(xp + 4);
                float2 c2 = *(const float2*)(xp + 8);
                float xv[10] = {a.x, a.y, a.z, a.w, b.x, b.y, b.z, b.w, c2.x, c2.y};
                const int cig = ch * CHUNK + ci;
                #pragma unroll
                for (int dx = 0; dx < 3; dx++) {
                    const ulonglong2* wp = (const ulonglong2*)
                        (w_s + (dy * 3 + dx) * (32 * 32) + cig * 32 + cg * 8);
                    ulonglong2 w01 = wp[0];
                    ulonglong2 w23 = wp[1];
                    #pragma unroll
                    for (int px = 0; px < 8; px++) {
                        uint64_t xs = pack2(xv[px + dx]);
                        ffma2(acc[px][0], xs, w01.x);
                        ffma2(acc[px][1], xs, w01.y);
                        ffma2(acc[px][2], xs, w23.x);
                        ffma2(acc[px][3], xs, w23.y);
                    }
                }
            }
        }
    }

    // epilogue
    const int R = R0 + row;
    if (R < H_OUT) {
        float4 b0 = *(const float4*)&bias[cg * 8];
        float4 b1 = *(const float4*)&bias[cg * 8 + 4];
        const float* act_row = g_active + (n * NBH + R / 14) * NBW;
        #pragma unroll
        for (int px = 0; px < 8; px++) {
            int C = C0 + c0 + px;
            if (C < W_OUT) {
                float f = act_row[C / 14];
                float lo0, hi0, lo1, hi1, lo2, hi2, lo3, hi3;
                unpack2(acc[px][0], lo0, hi0);
                unpack2(acc[px][1], lo1, hi1);
                unpack2(acc[px][2], lo2, hi2);
                unpack2(acc[px][3], lo3, hi3);
                float4 o0, o1;
                o0.x = (lo0 + b0.x) * f;  o0.y = (hi0 + b0.y) * f;
                o0.z = (lo1 + b0.z) * f;  o0.w = (hi1 + b0.w) * f;
                o1.x = (lo2 + b1.x) * f;  o1.y = (hi2 + b1.y) * f;
                o1.z = (lo3 + b1.z) * f;  o1.w = (hi3 + b1.w) * f;
                float* op = out + ((size_t)(n * H_OUT + R) * W_OUT + C) * COUT + cg * 8;
                ((float4*)op)[0] = o0;
                ((float4*)op)[1] = o1;
            }
        }
    }
}

// ---------------------------------------------------------------------------
extern "C" void kernel_launch(void* const* d_in, const int* in_sizes, int n_in,
                              void* d_out, int out_size)
{
    const float* x    = (const float*)d_in[0];
    const float* mask = (const float*)d_in[1];
    const float* kern = (const float*)d_in[2];
    const float* bias = (const float*)d_in[3];
    float* out = (float*)d_out;
    (void)in_sizes; (void)n_in; (void)out_size;

    cudaFuncSetAttribute(conv_kernel,
                         cudaFuncAttributeMaxDynamicSharedMemorySize, SMEM_BYTES);

    mask_kernel<<<N_IMG * NBH * NBW, 256>>>(mask);

    dim3 grid((W_OUT + TC - 1) / TC, (H_OUT + TR - 1) / TR, N_IMG);
    conv_kernel<<<grid, 256, SMEM_BYTES>>>(x, kern, bias, out);
}